// round 13
// baseline (speedup 1.0000x reference)
#include <cuda_runtime.h>
#include <cuda_fp16.h>
#include <cstdint>

#define N_NODES 100000
#define N_EDGES 600000
#define DD 128
#define TWD 768
#define RR 2
#define NSEG (N_NODES * RR)
#define XS 384   // fp16 activation buffer row stride: [x | m0 | m1]

// ---------------------------------------------------------------------------
// Scratch (device globals — no allocation allowed)
// ---------------------------------------------------------------------------
__device__ __half g_xA[(size_t)N_NODES * XS];   // 76.8 MB
__device__ __half g_xB[(size_t)N_NODES * XS];   // 76.8 MB
__device__ int    g_segcnt[NSEG];
__device__ int    g_segoff[NSEG];
__device__ int    g_cursor[NSEG];
__device__ int    g_esrc[N_EDGES];
__device__ int    g_part[256];

// Weight fragment blobs (fp16): per stage, hi plane then lo plane.
// Plane layout (uint4-packed): for k16-step s, j-pair j2, lane l:
//   uint4 at ((s*8 + j2)*32 + l) = { frag(j=2*j2, l), frag(j=2*j2+1, l) }
#define BLOB_TWEET 0
#define BLOB_WIN   196608
#define BLOB_COMB  229376
#define BLOB_WOUT1 327680
#define BLOB_TOTAL 360448
__device__ __half g_wblob[BLOB_TOTAL];

// ---------------------------------------------------------------------------
// PTX helpers (plain PTX: valid on sm_103 virtual target)
// ---------------------------------------------------------------------------
__device__ __forceinline__ void mma16816(float* c, const uint32_t* a, uint32_t b0, uint32_t b1) {
    asm volatile(
        "mma.sync.aligned.m16n8k16.row.col.f32.f16.f16.f32 "
        "{%0,%1,%2,%3}, {%4,%5,%6,%7}, {%8,%9}, {%0,%1,%2,%3};"
        : "+f"(c[0]), "+f"(c[1]), "+f"(c[2]), "+f"(c[3])
        : "r"(a[0]), "r"(a[1]), "r"(a[2]), "r"(a[3]), "r"(b0), "r"(b1));
}

__device__ __forceinline__ void ldmat4(uint32_t* d, uint32_t addr) {
    asm volatile("ldmatrix.sync.aligned.m8n8.x4.shared.b16 {%0,%1,%2,%3}, [%4];"
                 : "=r"(d[0]), "=r"(d[1]), "=r"(d[2]), "=r"(d[3]) : "r"(addr));
}

__device__ __forceinline__ void cp_async16(uint32_t dst, const void* src, int sz) {
    asm volatile("cp.async.ca.shared.global [%0], [%1], 16, %2;"
                 :: "r"(dst), "l"(src), "r"(sz));
}
__device__ __forceinline__ void cp_commit() { asm volatile("cp.async.commit_group;"); }
__device__ __forceinline__ void cp_wait0()  { asm volatile("cp.async.wait_group 0;" ::: "memory"); }

// fragment element index within a plane for element (k, n), uint4-packed layout
__device__ __forceinline__ int frag_idx(int k, int n) {
    int s = k >> 4;
    int j2 = n >> 4;                      // j-pair
    int jo = (n >> 3) & 1;                // which frag in the pair
    int lane = (n & 7) * 4 + ((k & 7) >> 1);
    return ((s * 8 + j2) * 32 + lane) * 8 + jo * 4 + ((k >> 3) & 1) * 2 + (k & 1);
}

// ---------------------------------------------------------------------------
// Weight prep: fp32 W[K,128] -> fp16 hi/lo fragment planes (uint4-packed)
// ---------------------------------------------------------------------------
__global__ void convert_weights(
    const float* __restrict__ Wt, const float* __restrict__ Wi,
    const float* __restrict__ root, const float* __restrict__ rw,
    const float* __restrict__ Wo1, __half* __restrict__ blob)
{
    int i = blockIdx.x * blockDim.x + threadIdx.x;
    if (i >= 1408 * 128) return;
    int n = i & 127;
    int kk = i >> 7;
    float w; int k, base, Kphys;
    if (kk < 768)       { k = kk;        base = BLOB_TWEET; Kphys = 768; w = Wt[k * 128 + n]; }
    else if (kk < 896)  { k = kk - 768;  base = BLOB_WIN;   Kphys = 128; w = Wi[k * 128 + n]; }
    else if (kk < 1280) { k = kk - 896;  base = BLOB_COMB;  Kphys = 384;
                          w = (k < 128) ? root[k * 128 + n] : rw[(size_t)(k - 128) * 128 + n]; }
    else                { k = kk - 1280; base = BLOB_WOUT1; Kphys = 128; w = Wo1[k * 128 + n]; }

    __half h = __float2half_rn(w);
    __half l = __float2half_rn(w - __half2float(h));
    int fi = frag_idx(k, n);
    blob[base + fi] = h;
    blob[base + Kphys * 128 + fi] = l;
}

// ---------------------------------------------------------------------------
// CSR build over (dst,rel) segments
// ---------------------------------------------------------------------------
__global__ void zeroseg(int* __restrict__ segcnt)
{
    int i = blockIdx.x * blockDim.x + threadIdx.x;
    if (i < NSEG) segcnt[i] = 0;
}

__global__ void count_edges(const int* __restrict__ dst, const int* __restrict__ et,
                            int* __restrict__ segcnt)
{
    int e = blockIdx.x * blockDim.x + threadIdx.x;
    if (e < N_EDGES) atomicAdd(&segcnt[dst[e] * RR + et[e]], 1);
}

__global__ void scanA(const int* __restrict__ segcnt, int* __restrict__ segoff,
                      int* __restrict__ part)
{
    __shared__ int s[1024];
    int tid = threadIdx.x;
    int i = blockIdx.x * 1024 + tid;
    int v = (i < NSEG) ? segcnt[i] : 0;
    s[tid] = v;
    __syncthreads();
#pragma unroll
    for (int d = 1; d < 1024; d <<= 1) {
        int t = (tid >= d) ? s[tid - d] : 0;
        __syncthreads();
        s[tid] += t;
        __syncthreads();
    }
    if (i < NSEG) segoff[i] = s[tid] - v;
    if (tid == 1023) part[blockIdx.x] = s[1023];
}

__global__ void scanB(int* __restrict__ part, int nb)
{
    __shared__ int s[256];
    int tid = threadIdx.x;
    int v = (tid < nb) ? part[tid] : 0;
    s[tid] = v;
    __syncthreads();
#pragma unroll
    for (int d = 1; d < 256; d <<= 1) {
        int t = (tid >= d) ? s[tid - d] : 0;
        __syncthreads();
        s[tid] += t;
        __syncthreads();
    }
    if (tid < nb) part[tid] = s[tid] - v;   // exclusive
}

__global__ void scanC(int* __restrict__ segoff, int* __restrict__ cursor,
                      const int* __restrict__ part)
{
    int i = blockIdx.x * 1024 + threadIdx.x;
    if (i < NSEG) {
        int o = segoff[i] + part[blockIdx.x];
        segoff[i] = o;
        cursor[i] = o;
    }
}

__global__ void scatter_edges(const int* __restrict__ src, const int* __restrict__ dst,
                              const int* __restrict__ et, int* __restrict__ cursor,
                              int* __restrict__ esrc)
{
    int e = blockIdx.x * blockDim.x + threadIdx.x;
    if (e >= N_EDGES) return;
    int seg = dst[e] * RR + et[e];
    int idx = atomicAdd(&cursor[seg], 1);
    esrc[idx] = src[e];
}

// ---------------------------------------------------------------------------
// Segment gather: mean over edges of x[src, 0:128] -> fp16 into the SAME
// buffer at cols 128 + rel*128.  64 threads (half2 lanes) per segment.
// ---------------------------------------------------------------------------
__global__ __launch_bounds__(256) void gather_agg(
    const int* __restrict__ esrc, const int* __restrict__ segoff,
    const int* __restrict__ segcnt, __half2* __restrict__ x2)
{
    int seg = blockIdx.x * 4 + (threadIdx.x >> 6);
    int t = threadIdx.x & 63;
    if (seg >= NSEG) return;
    int n = __ldg(&segcnt[seg]);
    int off = __ldg(&segoff[seg]);
    float ax = 0.f, ay = 0.f;
    int j = 0;
    for (; j + 2 <= n; j += 2) {
        int s0 = __ldg(&esrc[off + j]);
        int s1 = __ldg(&esrc[off + j + 1]);
        __half2 h0 = __ldg(&x2[(size_t)s0 * (XS / 2) + t]);
        __half2 h1 = __ldg(&x2[(size_t)s1 * (XS / 2) + t]);
        float2 f0 = __half22float2(h0);
        float2 f1 = __half22float2(h1);
        ax += f0.x + f1.x;
        ay += f0.y + f1.y;
    }
    if (j < n) {
        int s0 = __ldg(&esrc[off + j]);
        float2 f0 = __half22float2(__ldg(&x2[(size_t)s0 * (XS / 2) + t]));
        ax += f0.x;
        ay += f0.y;
    }
    float inv = 1.f / fmaxf((float)n, 1.f);
    x2[(size_t)(seg >> 1) * (XS / 2) + 64 + (seg & 1) * 64 + t] =
        __floats2half2_rn(ax * inv, ay * inv);
}

// ---------------------------------------------------------------------------
// HMMA GEMM: C = act( concat(A1h[fp16, stride As], A1f[fp32])[M,Kphys] @ W + bias )
// B fragments loaded as coalesced uint4 (2 j-tiles per load).
// useLo: include B lo-plane correction MMAs. If W2 != null: fused final
// projection — atomicAdd act(C)@W2 into Out2 (pre-initialized with b2);
// otherwise store fp16 into Ch with row stride Cs.
// ---------------------------------------------------------------------------
__global__ __launch_bounds__(256, 2) void mma_gemm(
    const __half* __restrict__ A1h, int As, int K1,
    const float* __restrict__ A1f, int K1f,
    const __half* __restrict__ Wblob, int Kphys, int useLo,
    const float* __restrict__ bias,
    __half* __restrict__ Ch, int Cs,
    const float* __restrict__ W2, float* __restrict__ Out2,
    int M, int act)
{
    __shared__ __half Ah[2][128][40];

    const int tid = threadIdx.x;
    const int wid = tid >> 5;
    const int lane = tid & 31;
    const int wr = wid & 3;           // 32-row group
    const int wc = wid >> 2;          // 64-col group
    const int row0 = blockIdx.x * 128;

    const uint4* __restrict__ BH4 = (const uint4*)Wblob;
    const uint4* __restrict__ BL4 = (const uint4*)(Wblob + (size_t)Kphys * 128);

    float acc[2][8][4];
#pragma unroll
    for (int mt = 0; mt < 2; mt++)
#pragma unroll
        for (int j = 0; j < 8; j++)
#pragma unroll
            for (int q = 0; q < 4; q++) acc[mt][j][q] = 0.f;

    const uint32_t ah_base = (uint32_t)__cvta_generic_to_shared(&Ah[0][0][0]);
    const uint32_t bufstride = 128 * 80;   // bytes per buffer

    float f[16];   // staging for fp32-source chunks

    auto loadA = [&](int c, int b) {
        const int kp = c << 5;
        if (kp < K1) {
#pragma unroll
            for (int p = 0; p < 2; p++) {
                int row = (tid >> 2) + p * 64;
                int gr = row0 + row;
                uint32_t dst = ah_base + b * bufstride + row * 80 + (tid & 3) * 16;
                const __half* src = A1h + (size_t)gr * As + kp + (tid & 3) * 8;
                cp_async16(dst, src, (gr < M) ? 16 : 0);
            }
            cp_commit();
        } else {
#pragma unroll
            for (int p = 0; p < 4; p++) {
                int row = (tid >> 3) + p * 32;
                int gr = row0 + row;
                int ks = (tid & 7) * 4;
                float4 v = make_float4(0.f, 0.f, 0.f, 0.f);
                if (gr < M) {
                    int ka = kp - K1 + ks;
                    v = *(const float4*)&A1f[(size_t)gr * K1f + ka];
                }
                f[p * 4 + 0] = v.x; f[p * 4 + 1] = v.y;
                f[p * 4 + 2] = v.z; f[p * 4 + 3] = v.w;
            }
        }
    };
    auto storeA = [&](int c, int b) {
        const int kp = c << 5;
        if (kp >= K1) {
#pragma unroll
            for (int p = 0; p < 4; p++) {
                int row = (tid >> 3) + p * 32;
                int ks = (tid & 7) * 4;
                __half2 h0, h1;
                h0.x = __float2half_rn(f[p * 4 + 0]);
                h0.y = __float2half_rn(f[p * 4 + 1]);
                h1.x = __float2half_rn(f[p * 4 + 2]);
                h1.y = __float2half_rn(f[p * 4 + 3]);
                uint2* dst = (uint2*)&Ah[b][row][ks];
                *dst = make_uint2(*(uint32_t*)&h0, *(uint32_t*)&h1);
            }
        }
    };

    const int nChunks = Kphys >> 5;
    loadA(0, 0);
    storeA(0, 0);
    cp_wait0();
    __syncthreads();

    for (int c = 0; c < nChunks; c++) {
        const int cur = c & 1;
        const bool more = (c + 1) < nChunks;
        if (more) loadA(c + 1, cur ^ 1);

#pragma unroll
        for (int s = 0; s < 2; s++) {
            const int sg = c * 2 + s;

            uint32_t af[2][4];
            const int mrow = lane & 15;
            const int mk = (s << 4) + ((lane >> 4) << 3);
#pragma unroll
            for (int mt = 0; mt < 2; mt++) {
                uint32_t off = cur * bufstride + (uint32_t)((wr * 32 + mt * 16 + mrow) * 80 + mk * 2);
                ldmat4(af[mt], ah_base + off);
            }

            // B fragments: 4 coalesced uint4 loads = 8 j-tiles (hi plane)
            const uint4* bh = BH4 + ((size_t)sg * 8 + wc * 4) * 32 + lane;
            uint4 h4[4];
#pragma unroll
            for (int i = 0; i < 4; i++) h4[i] = __ldg(&bh[i * 32]);
#pragma unroll
            for (int i = 0; i < 4; i++) {
                mma16816(acc[0][2 * i],     af[0], h4[i].x, h4[i].y);
                mma16816(acc[1][2 * i],     af[1], h4[i].x, h4[i].y);
                mma16816(acc[0][2 * i + 1], af[0], h4[i].z, h4[i].w);
                mma16816(acc[1][2 * i + 1], af[1], h4[i].z, h4[i].w);
            }
            if (useLo) {
                const uint4* bl = BL4 + ((size_t)sg * 8 + wc * 4) * 32 + lane;
                uint4 l4[4];
#pragma unroll
                for (int i = 0; i < 4; i++) l4[i] = __ldg(&bl[i * 32]);
#pragma unroll
                for (int i = 0; i < 4; i++) {
                    mma16816(acc[0][2 * i],     af[0], l4[i].x, l4[i].y);
                    mma16816(acc[1][2 * i],     af[1], l4[i].x, l4[i].y);
                    mma16816(acc[0][2 * i + 1], af[0], l4[i].z, l4[i].w);
                    mma16816(acc[1][2 * i + 1], af[1], l4[i].z, l4[i].w);
                }
            }
        }

        if (more) storeA(c + 1, cur ^ 1);
        cp_wait0();
        __syncthreads();
    }

    // ---- epilogue ----
#pragma unroll
    for (int mt = 0; mt < 2; mt++) {
        float p00 = 0.f, p01 = 0.f, p10 = 0.f, p11 = 0.f;  // fused-out partials
#pragma unroll
        for (int j = 0; j < 8; j++) {
            int col = wc * 64 + j * 8 + (lane & 3) * 2;
            int r0 = row0 + wr * 32 + mt * 16 + (lane >> 2);
            float b0 = __ldg(&bias[col]), b1 = __ldg(&bias[col + 1]);
            float v0 = acc[mt][j][0] + b0, v1 = acc[mt][j][1] + b1;
            float v2 = acc[mt][j][2] + b0, v3 = acc[mt][j][3] + b1;
            if (act) {
                v0 = (v0 > 0.f) ? v0 : 0.01f * v0;
                v1 = (v1 > 0.f) ? v1 : 0.01f * v1;
                v2 = (v2 > 0.f) ? v2 : 0.01f * v2;
                v3 = (v3 > 0.f) ? v3 : 0.01f * v3;
            }
            if (W2) {
                float w00 = __ldg(&W2[col * 2 + 0]), w01 = __ldg(&W2[col * 2 + 1]);
                float w10 = __ldg(&W2[col * 2 + 2]), w11 = __ldg(&W2[col * 2 + 3]);
                p00 += v0 * w00 + v1 * w10;
                p01 += v0 * w01 + v1 * w11;
                p10 += v2 * w00 + v3 * w10;
                p11 += v2 * w01 + v3 * w11;
            } else {
                __half2 q0 = __floats2half2_rn(v0, v1);
                __half2 q1 = __floats2half2_rn(v2, v3);
                if (r0 < M)     *(__half2*)&Ch[(size_t)r0 * Cs + col]       = q0;
                if (r0 + 8 < M) *(__half2*)&Ch[(size_t)(r0 + 8) * Cs + col] = q1;
            }
        }
        if (W2) {
#pragma unroll
            for (int off = 1; off <= 2; off <<= 1) {
                p00 += __shfl_xor_sync(0xFFFFFFFFu, p00, off);
                p01 += __shfl_xor_sync(0xFFFFFFFFu, p01, off);
                p10 += __shfl_xor_sync(0xFFFFFFFFu, p10, off);
                p11 += __shfl_xor_sync(0xFFFFFFFFu, p11, off);
            }
            if ((lane & 3) == 0) {
                int r0 = row0 + wr * 32 + mt * 16 + (lane >> 2);
                if (r0 < M) {
                    atomicAdd(&Out2[(size_t)r0 * 2 + 0], p00);
                    atomicAdd(&Out2[(size_t)r0 * 2 + 1], p01);
                }
                if (r0 + 8 < M) {
                    atomicAdd(&Out2[(size_t)(r0 + 8) * 2 + 0], p10);
                    atomicAdd(&Out2[(size_t)(r0 + 8) * 2 + 1], p11);
                }
            }
        }
    }
}

// ---------------------------------------------------------------------------
__global__ void init_out(float* __restrict__ out, const float* __restrict__ b2)
{
    int i = blockIdx.x * blockDim.x + threadIdx.x;
    if (i < N_NODES * 2) out[i] = __ldg(&b2[i & 1]);
}

// ---------------------------------------------------------------------------
extern "C" void kernel_launch(void* const* d_in, const int* in_sizes, int n_in,
                              void* d_out, int out_size)
{
    const float* tweet     = (const float*)d_in[1];
    const int*   ei        = (const int*)d_in[4];
    const int*   etype     = (const int*)d_in[5];
    const float* W_tweet   = (const float*)d_in[6];
    const float* b_tweet   = (const float*)d_in[7];
    const float* W_in      = (const float*)d_in[8];
    const float* b_in      = (const float*)d_in[9];
    const float* rgcn_w    = (const float*)d_in[10];
    const float* rgcn_root = (const float*)d_in[11];
    const float* rgcn_b    = (const float*)d_in[12];
    const float* W_out1    = (const float*)d_in[13];
    const float* b_out1    = (const float*)d_in[14];
    const float* W_out2    = (const float*)d_in[15];
    const float* b_out2    = (const float*)d_in[16];
    float* out = (float*)d_out;

    int *segcnt, *segoff, *cursor, *esrc, *part;
    __half *xA, *xB, *blob;
    cudaGetSymbolAddress((void**)&xA, g_xA);
    cudaGetSymbolAddress((void**)&xB, g_xB);
    cudaGetSymbolAddress((void**)&segcnt, g_segcnt);
    cudaGetSymbolAddress((void**)&segoff, g_segoff);
    cudaGetSymbolAddress((void**)&cursor, g_cursor);
    cudaGetSymbolAddress((void**)&esrc, g_esrc);
    cudaGetSymbolAddress((void**)&part, g_part);
    cudaGetSymbolAddress((void**)&blob, g_wblob);

    const int M = N_NODES;
    const int gemm_blocks = (M + 127) / 128;
    const int scan_blocks = (NSEG + 1023) / 1024;   // 196

    const int* src = ei;
    const int* dst = ei + N_EDGES;

    // Fork a side stream for the CSR build + out init (independent of the
    // first two GEMMs). Recorded into the graph as parallel branches.
    cudaStream_t s2;
    cudaStreamCreateWithFlags(&s2, cudaStreamNonBlocking);
    cudaEvent_t eFork, eJoin;
    cudaEventCreateWithFlags(&eFork, cudaEventDisableTiming);
    cudaEventCreateWithFlags(&eJoin, cudaEventDisableTiming);

    cudaEventRecord(eFork, 0);
    cudaStreamWaitEvent(s2, eFork, 0);
    zeroseg<<<(NSEG + 255) / 256, 256, 0, s2>>>(segcnt);
    count_edges<<<(N_EDGES + 255) / 256, 256, 0, s2>>>(dst, etype, segcnt);
    scanA<<<scan_blocks, 1024, 0, s2>>>(segcnt, segoff, part);
    scanB<<<1, 256, 0, s2>>>(part, scan_blocks);
    scanC<<<scan_blocks, 1024, 0, s2>>>(segoff, cursor, part);
    scatter_edges<<<(N_EDGES + 255) / 256, 256, 0, s2>>>(src, dst, etype, cursor, esrc);
    init_out<<<(N_NODES * 2 + 255) / 256, 256, 0, s2>>>(out, b_out2);
    cudaEventRecord(eJoin, s2);

    // Main stream: weight prep + first two GEMMs (overlap the CSR branch)
    convert_weights<<<(1408 * 128 + 255) / 256, 256>>>(W_tweet, W_in, rgcn_root, rgcn_w, W_out1, blob);

    // t = lrelu(tweet @ W_tweet + b)  : fp32 in -> xA[:,0:128], B hi-plane only
    mma_gemm<<<gemm_blocks, 256>>>(nullptr, 0, 0, tweet, TWD,
                                   blob + BLOB_TWEET, TWD, 0, b_tweet,
                                   xA, XS, nullptr, nullptr, M, 1);
    // x = lrelu(t @ W_in + b)  : xA[:,0:128] -> xB[:,0:128], 2-term B
    mma_gemm<<<gemm_blocks, 256>>>(xA, XS, DD, nullptr, 0,
                                   blob + BLOB_WIN, DD, 1, b_in,
                                   xB, XS, nullptr, nullptr, M, 1);

    // Join: gathers need the CSR; final GEMM needs init_out
    cudaStreamWaitEvent(0, eJoin, 0);

    // conv1: means into xB[:,128:384]; combine xB[:,0:384] -> xA[:,0:128]
    gather_agg<<<(NSEG + 3) / 4, 256>>>(esrc, segoff, segcnt, (__half2*)xB);
    mma_gemm<<<gemm_blocks, 256>>>(xB, XS, 3 * DD, nullptr, 0,
                                   blob + BLOB_COMB, 3 * DD, 0, rgcn_b,
                                   xA, XS, nullptr, nullptr, M, 0);

    // conv2: means into xA[:,128:384]; combine xA[:,0:384] -> xB[:,0:128]
    gather_agg<<<(NSEG + 3) / 4, 256>>>(esrc, segoff, segcnt, (__half2*)xA);
    mma_gemm<<<gemm_blocks, 256>>>(xA, XS, 3 * DD, nullptr, 0,
                                   blob + BLOB_COMB, 3 * DD, 1, rgcn_b,
                                   xB, XS, nullptr, nullptr, M, 0);

    // fused: out = lrelu(xB[:,0:128] @ W_out1 + b_out1) @ W_out2 + b_out2
    mma_gemm<<<gemm_blocks, 256>>>(xB, XS, DD, nullptr, 0,
                                   blob + BLOB_WOUT1, DD, 1, b_out1,
                                   nullptr, 0, W_out2, out, M, 1);

    cudaEventDestroy(eFork);
    cudaEventDestroy(eJoin);
    cudaStreamDestroy(s2);
}

// round 14
// speedup vs baseline: 1.0957x; 1.0957x over previous
#include <cuda_runtime.h>
#include <cuda_fp16.h>
#include <cstdint>

#define N_NODES 100000
#define N_EDGES 600000
#define DD 128
#define TWD 768
#define RR 2
#define NSEG (N_NODES * RR)
#define XS 384   // fp16 activation buffer row stride: [x | m0 | m1]

// ---------------------------------------------------------------------------
// Scratch (device globals — no allocation allowed)
// ---------------------------------------------------------------------------
__device__ __half g_xA[(size_t)N_NODES * XS];   // 76.8 MB
__device__ __half g_xB[(size_t)N_NODES * XS];   // 76.8 MB
__device__ int    g_segcnt[NSEG];
__device__ int    g_segoff[NSEG];
__device__ int    g_cursor[NSEG];
__device__ int    g_esrc[N_EDGES];
__device__ int    g_part[256];

// Weight fragment blobs (fp16): per stage, hi plane then lo plane.
// Plane layout (uint2 per (k16-step s, n8-tile j, lane)): idx = ((s*16+j)*32+lane)
#define BLOB_TWEET 0
#define BLOB_WIN   196608
#define BLOB_COMB  229376
#define BLOB_WOUT1 327680
#define BLOB_TOTAL 360448
__device__ __half g_wblob[BLOB_TOTAL];

// ---------------------------------------------------------------------------
// PTX helpers (plain PTX: valid on sm_103 virtual target)
// ---------------------------------------------------------------------------
__device__ __forceinline__ void mma16816(float* c, const uint32_t* a, uint2 b) {
    asm volatile(
        "mma.sync.aligned.m16n8k16.row.col.f32.f16.f16.f32 "
        "{%0,%1,%2,%3}, {%4,%5,%6,%7}, {%8,%9}, {%0,%1,%2,%3};"
        : "+f"(c[0]), "+f"(c[1]), "+f"(c[2]), "+f"(c[3])
        : "r"(a[0]), "r"(a[1]), "r"(a[2]), "r"(a[3]), "r"(b.x), "r"(b.y));
}

__device__ __forceinline__ void ldmat4(uint32_t* d, uint32_t addr) {
    asm volatile("ldmatrix.sync.aligned.m8n8.x4.shared.b16 {%0,%1,%2,%3}, [%4];"
                 : "=r"(d[0]), "=r"(d[1]), "=r"(d[2]), "=r"(d[3]) : "r"(addr));
}

__device__ __forceinline__ void cp_async16(uint32_t dst, const void* src, int sz) {
    asm volatile("cp.async.ca.shared.global [%0], [%1], 16, %2;"
                 :: "r"(dst), "l"(src), "r"(sz));
}
__device__ __forceinline__ void cp_commit() { asm volatile("cp.async.commit_group;"); }
__device__ __forceinline__ void cp_wait0()  { asm volatile("cp.async.wait_group 0;" ::: "memory"); }

// fragment index (fp16 elems within a plane) for element (k, n) — uint2 layout
__device__ __forceinline__ int frag_idx(int k, int n) {
    int s = k >> 4, j = n >> 3;
    int lane = (n & 7) * 4 + ((k & 7) >> 1);
    return ((((s * 16 + j) * 32 + lane) * 2 + ((k >> 3) & 1)) << 1) + (k & 1);
}

// ---------------------------------------------------------------------------
// Weight prep: fp32 W[K,128] -> fp16 hi/lo fragment planes
// ---------------------------------------------------------------------------
__global__ void convert_weights(
    const float* __restrict__ Wt, const float* __restrict__ Wi,
    const float* __restrict__ root, const float* __restrict__ rw,
    const float* __restrict__ Wo1, __half* __restrict__ blob)
{
    int i = blockIdx.x * blockDim.x + threadIdx.x;
    if (i >= 1408 * 128) return;
    int n = i & 127;
    int kk = i >> 7;
    float w; int k, base, Kphys;
    if (kk < 768)       { k = kk;        base = BLOB_TWEET; Kphys = 768; w = Wt[k * 128 + n]; }
    else if (kk < 896)  { k = kk - 768;  base = BLOB_WIN;   Kphys = 128; w = Wi[k * 128 + n]; }
    else if (kk < 1280) { k = kk - 896;  base = BLOB_COMB;  Kphys = 384;
                          w = (k < 128) ? root[k * 128 + n] : rw[(size_t)(k - 128) * 128 + n]; }
    else                { k = kk - 1280; base = BLOB_WOUT1; Kphys = 128; w = Wo1[k * 128 + n]; }

    __half h = __float2half_rn(w);
    __half l = __float2half_rn(w - __half2float(h));
    int fi = frag_idx(k, n);
    blob[base + fi] = h;
    blob[base + Kphys * 128 + fi] = l;
}

// ---------------------------------------------------------------------------
// CSR build over (dst,rel) segments
// ---------------------------------------------------------------------------
__global__ void zeroseg(int* __restrict__ segcnt)
{
    int i = blockIdx.x * blockDim.x + threadIdx.x;
    if (i < NSEG) segcnt[i] = 0;
}

__global__ void count_edges(const int* __restrict__ dst, const int* __restrict__ et,
                            int* __restrict__ segcnt)
{
    int e = blockIdx.x * blockDim.x + threadIdx.x;
    if (e < N_EDGES) atomicAdd(&segcnt[dst[e] * RR + et[e]], 1);
}

__global__ void scanA(const int* __restrict__ segcnt, int* __restrict__ segoff,
                      int* __restrict__ part)
{
    __shared__ int s[1024];
    int tid = threadIdx.x;
    int i = blockIdx.x * 1024 + tid;
    int v = (i < NSEG) ? segcnt[i] : 0;
    s[tid] = v;
    __syncthreads();
#pragma unroll
    for (int d = 1; d < 1024; d <<= 1) {
        int t = (tid >= d) ? s[tid - d] : 0;
        __syncthreads();
        s[tid] += t;
        __syncthreads();
    }
    if (i < NSEG) segoff[i] = s[tid] - v;
    if (tid == 1023) part[blockIdx.x] = s[1023];
}

__global__ void scanB(int* __restrict__ part, int nb)
{
    __shared__ int s[256];
    int tid = threadIdx.x;
    int v = (tid < nb) ? part[tid] : 0;
    s[tid] = v;
    __syncthreads();
#pragma unroll
    for (int d = 1; d < 256; d <<= 1) {
        int t = (tid >= d) ? s[tid - d] : 0;
        __syncthreads();
        s[tid] += t;
        __syncthreads();
    }
    if (tid < nb) part[tid] = s[tid] - v;   // exclusive
}

__global__ void scanC(int* __restrict__ segoff, int* __restrict__ cursor,
                      const int* __restrict__ part)
{
    int i = blockIdx.x * 1024 + threadIdx.x;
    if (i < NSEG) {
        int o = segoff[i] + part[blockIdx.x];
        segoff[i] = o;
        cursor[i] = o;
    }
}

__global__ void scatter_edges(const int* __restrict__ src, const int* __restrict__ dst,
                              const int* __restrict__ et, int* __restrict__ cursor,
                              int* __restrict__ esrc)
{
    int e = blockIdx.x * blockDim.x + threadIdx.x;
    if (e >= N_EDGES) return;
    int seg = dst[e] * RR + et[e];
    int idx = atomicAdd(&cursor[seg], 1);
    esrc[idx] = src[e];
}

// ---------------------------------------------------------------------------
// Segment gather: mean over edges of x[src, 0:128] -> fp16 into the SAME
// buffer at cols 128 + rel*128.  64 threads (half2 lanes) per segment.
// ---------------------------------------------------------------------------
__global__ __launch_bounds__(256) void gather_agg(
    const int* __restrict__ esrc, const int* __restrict__ segoff,
    const int* __restrict__ segcnt, __half2* __restrict__ x2)
{
    int seg = blockIdx.x * 4 + (threadIdx.x >> 6);
    int t = threadIdx.x & 63;
    if (seg >= NSEG) return;
    int n = __ldg(&segcnt[seg]);
    int off = __ldg(&segoff[seg]);
    float ax = 0.f, ay = 0.f;
    int j = 0;
    for (; j + 2 <= n; j += 2) {
        int s0 = __ldg(&esrc[off + j]);
        int s1 = __ldg(&esrc[off + j + 1]);
        __half2 h0 = __ldg(&x2[(size_t)s0 * (XS / 2) + t]);
        __half2 h1 = __ldg(&x2[(size_t)s1 * (XS / 2) + t]);
        float2 f0 = __half22float2(h0);
        float2 f1 = __half22float2(h1);
        ax += f0.x + f1.x;
        ay += f0.y + f1.y;
    }
    if (j < n) {
        int s0 = __ldg(&esrc[off + j]);
        float2 f0 = __half22float2(__ldg(&x2[(size_t)s0 * (XS / 2) + t]));
        ax += f0.x;
        ay += f0.y;
    }
    float inv = 1.f / fmaxf((float)n, 1.f);
    x2[(size_t)(seg >> 1) * (XS / 2) + 64 + (seg & 1) * 64 + t] =
        __floats2half2_rn(ax * inv, ay * inv);
}

// ---------------------------------------------------------------------------
// HMMA GEMM (template on K-chunk): C = act( A[M,Kphys] @ W + bias )
// A is either pure fp16 (stride As; CHUNK=64) or pure fp32 (CHUNK=32).
// B fragments: uint2 layout (R12-best). useLo: 2-term B split.
// If W2 != null: fused final projection into Out2 (pre-initialized with b2).
// ---------------------------------------------------------------------------
template<int CHUNK>
__global__ __launch_bounds__(256, 2) void mma_gemm(
    const __half* __restrict__ A1h, int As, int K1,
    const float* __restrict__ A1f, int K1f,
    const __half* __restrict__ Wblob, int Kphys, int useLo,
    const float* __restrict__ bias,
    __half* __restrict__ Ch, int Cs,
    const float* __restrict__ W2, float* __restrict__ Out2,
    int M, int act)
{
    constexpr int PAD = 8;
    constexpr int RS = CHUNK + PAD;              // smem row stride (halves)
    constexpr int STEPS = CHUNK / 16;            // k16-steps per chunk
    __shared__ __half Ah[2][128][RS];

    const int tid = threadIdx.x;
    const int wid = tid >> 5;
    const int lane = tid & 31;
    const int wr = wid & 3;           // 32-row group
    const int wc = wid >> 2;          // 64-col group
    const int row0 = blockIdx.x * 128;

    const uint2* __restrict__ BH = (const uint2*)Wblob;
    const uint2* __restrict__ BL = (const uint2*)(Wblob + (size_t)Kphys * 128);

    float acc[2][8][4];
#pragma unroll
    for (int mt = 0; mt < 2; mt++)
#pragma unroll
        for (int j = 0; j < 8; j++)
#pragma unroll
            for (int q = 0; q < 4; q++) acc[mt][j][q] = 0.f;

    const uint32_t ah_base = (uint32_t)__cvta_generic_to_shared(&Ah[0][0][0]);
    const uint32_t bufstride = 128 * RS * 2;     // bytes per buffer

    float f[16];   // staging for fp32-source chunks (CHUNK=32 only)

    auto loadA = [&](int c, int b) {
        const int kp = c * CHUNK;
        if (kp < K1) {
            // fp16 source: 2 threads/row, each CHUNK/16 x 16B cps
            const int row = tid >> 1;
            const int hs = tid & 1;
            const int gr = row0 + row;
            const int ok = (gr < M) ? 16 : 0;
#pragma unroll
            for (int p = 0; p < CHUNK / 16; p++) {
                int coloff = hs * (CHUNK / 2) + p * 8;
                uint32_t dst = ah_base + b * bufstride + row * (RS * 2) + coloff * 2;
                const __half* src = A1h + (size_t)gr * As + kp + coloff;
                cp_async16(dst, src, ok);
            }
            cp_commit();
        } else if (CHUNK == 32) {
            // fp32 source: 8 lanes x float4 per row, 4 passes
#pragma unroll
            for (int p = 0; p < 4; p++) {
                int row = (tid >> 3) + p * 32;
                int gr = row0 + row;
                int ks = (tid & 7) * 4;
                float4 v = make_float4(0.f, 0.f, 0.f, 0.f);
                if (gr < M) {
                    int ka = kp - K1 + ks;
                    v = *(const float4*)&A1f[(size_t)gr * K1f + ka];
                }
                f[p * 4 + 0] = v.x; f[p * 4 + 1] = v.y;
                f[p * 4 + 2] = v.z; f[p * 4 + 3] = v.w;
            }
        }
    };
    auto storeA = [&](int c, int b) {
        const int kp = c * CHUNK;
        if (CHUNK == 32 && kp >= K1) {
#pragma unroll
            for (int p = 0; p < 4; p++) {
                int row = (tid >> 3) + p * 32;
                int ks = (tid & 7) * 4;
                __half2 h0, h1;
                h0.x = __float2half_rn(f[p * 4 + 0]);
                h0.y = __float2half_rn(f[p * 4 + 1]);
                h1.x = __float2half_rn(f[p * 4 + 2]);
                h1.y = __float2half_rn(f[p * 4 + 3]);
                uint2* dst = (uint2*)&Ah[b][row][ks];
                *dst = make_uint2(*(uint32_t*)&h0, *(uint32_t*)&h1);
            }
        }
    };

    const int nChunks = Kphys / CHUNK;
    loadA(0, 0);
    storeA(0, 0);
    cp_wait0();
    __syncthreads();

    for (int c = 0; c < nChunks; c++) {
        const int cur = c & 1;
        const bool more = (c + 1) < nChunks;
        if (more) loadA(c + 1, cur ^ 1);

#pragma unroll
        for (int s = 0; s < STEPS; s++) {
            const int sg = c * STEPS + s;
            const uint2* bh = BH + ((size_t)sg * 16 + wc * 8) * 32 + lane;
            const uint2* bl = BL + ((size_t)sg * 16 + wc * 8) * 32 + lane;

            uint32_t af[2][4];
            const int mrow = lane & 15;
            const int mk = (s << 4) + ((lane >> 4) << 3);
#pragma unroll
            for (int mt = 0; mt < 2; mt++) {
                uint32_t off = cur * bufstride + (uint32_t)((wr * 32 + mt * 16 + mrow) * (RS * 2) + mk * 2);
                ldmat4(af[mt], ah_base + off);
            }
            uint2 vh[8];
#pragma unroll
            for (int j = 0; j < 8; j++) vh[j] = __ldg(&bh[j * 32]);
#pragma unroll
            for (int j = 0; j < 8; j++) {
                mma16816(acc[0][j], af[0], vh[j]);
                mma16816(acc[1][j], af[1], vh[j]);
            }
            if (useLo) {
#pragma unroll
                for (int j = 0; j < 8; j++) vh[j] = __ldg(&bl[j * 32]);
#pragma unroll
                for (int j = 0; j < 8; j++) {
                    mma16816(acc[0][j], af[0], vh[j]);
                    mma16816(acc[1][j], af[1], vh[j]);
                }
            }
        }

        if (more) storeA(c + 1, cur ^ 1);
        cp_wait0();
        __syncthreads();
    }

    // ---- epilogue ----
#pragma unroll
    for (int mt = 0; mt < 2; mt++) {
        float p00 = 0.f, p01 = 0.f, p10 = 0.f, p11 = 0.f;  // fused-out partials
#pragma unroll
        for (int j = 0; j < 8; j++) {
            int col = wc * 64 + j * 8 + (lane & 3) * 2;
            int r0 = row0 + wr * 32 + mt * 16 + (lane >> 2);
            float b0 = __ldg(&bias[col]), b1 = __ldg(&bias[col + 1]);
            float v0 = acc[mt][j][0] + b0, v1 = acc[mt][j][1] + b1;
            float v2 = acc[mt][j][2] + b0, v3 = acc[mt][j][3] + b1;
            if (act) {
                v0 = (v0 > 0.f) ? v0 : 0.01f * v0;
                v1 = (v1 > 0.f) ? v1 : 0.01f * v1;
                v2 = (v2 > 0.f) ? v2 : 0.01f * v2;
                v3 = (v3 > 0.f) ? v3 : 0.01f * v3;
            }
            if (W2) {
                float w00 = __ldg(&W2[col * 2 + 0]), w01 = __ldg(&W2[col * 2 + 1]);
                float w10 = __ldg(&W2[col * 2 + 2]), w11 = __ldg(&W2[col * 2 + 3]);
                p00 += v0 * w00 + v1 * w10;
                p01 += v0 * w01 + v1 * w11;
                p10 += v2 * w00 + v3 * w10;
                p11 += v2 * w01 + v3 * w11;
            } else {
                __half2 q0 = __floats2half2_rn(v0, v1);
                __half2 q1 = __floats2half2_rn(v2, v3);
                if (r0 < M)     *(__half2*)&Ch[(size_t)r0 * Cs + col]       = q0;
                if (r0 + 8 < M) *(__half2*)&Ch[(size_t)(r0 + 8) * Cs + col] = q1;
            }
        }
        if (W2) {
#pragma unroll
            for (int off = 1; off <= 2; off <<= 1) {
                p00 += __shfl_xor_sync(0xFFFFFFFFu, p00, off);
                p01 += __shfl_xor_sync(0xFFFFFFFFu, p01, off);
                p10 += __shfl_xor_sync(0xFFFFFFFFu, p10, off);
                p11 += __shfl_xor_sync(0xFFFFFFFFu, p11, off);
            }
            if ((lane & 3) == 0) {
                int r0 = row0 + wr * 32 + mt * 16 + (lane >> 2);
                if (r0 < M) {
                    atomicAdd(&Out2[(size_t)r0 * 2 + 0], p00);
                    atomicAdd(&Out2[(size_t)r0 * 2 + 1], p01);
                }
                if (r0 + 8 < M) {
                    atomicAdd(&Out2[(size_t)(r0 + 8) * 2 + 0], p10);
                    atomicAdd(&Out2[(size_t)(r0 + 8) * 2 + 1], p11);
                }
            }
        }
    }
}

// ---------------------------------------------------------------------------
__global__ void init_out(float* __restrict__ out, const float* __restrict__ b2)
{
    int i = blockIdx.x * blockDim.x + threadIdx.x;
    if (i < N_NODES * 2) out[i] = __ldg(&b2[i & 1]);
}

// ---------------------------------------------------------------------------
extern "C" void kernel_launch(void* const* d_in, const int* in_sizes, int n_in,
                              void* d_out, int out_size)
{
    const float* tweet     = (const float*)d_in[1];
    const int*   ei        = (const int*)d_in[4];
    const int*   etype     = (const int*)d_in[5];
    const float* W_tweet   = (const float*)d_in[6];
    const float* b_tweet   = (const float*)d_in[7];
    const float* W_in      = (const float*)d_in[8];
    const float* b_in      = (const float*)d_in[9];
    const float* rgcn_w    = (const float*)d_in[10];
    const float* rgcn_root = (const float*)d_in[11];
    const float* rgcn_b    = (const float*)d_in[12];
    const float* W_out1    = (const float*)d_in[13];
    const float* b_out1    = (const float*)d_in[14];
    const float* W_out2    = (const float*)d_in[15];
    const float* b_out2    = (const float*)d_in[16];
    float* out = (float*)d_out;

    int *segcnt, *segoff, *cursor, *esrc, *part;
    __half *xA, *xB, *blob;
    cudaGetSymbolAddress((void**)&xA, g_xA);
    cudaGetSymbolAddress((void**)&xB, g_xB);
    cudaGetSymbolAddress((void**)&segcnt, g_segcnt);
    cudaGetSymbolAddress((void**)&segoff, g_segoff);
    cudaGetSymbolAddress((void**)&cursor, g_cursor);
    cudaGetSymbolAddress((void**)&esrc, g_esrc);
    cudaGetSymbolAddress((void**)&part, g_part);
    cudaGetSymbolAddress((void**)&blob, g_wblob);

    const int M = N_NODES;
    const int gemm_blocks = (M + 127) / 128;
    const int scan_blocks = (NSEG + 1023) / 1024;   // 196

    const int* src = ei;
    const int* dst = ei + N_EDGES;

    // Fork a side stream for the CSR build + out init (independent of the
    // first two GEMMs). Recorded into the graph as parallel branches.
    cudaStream_t s2;
    cudaStreamCreateWithFlags(&s2, cudaStreamNonBlocking);
    cudaEvent_t eFork, eJoin;
    cudaEventCreateWithFlags(&eFork, cudaEventDisableTiming);
    cudaEventCreateWithFlags(&eJoin, cudaEventDisableTiming);

    cudaEventRecord(eFork, 0);
    cudaStreamWaitEvent(s2, eFork, 0);
    zeroseg<<<(NSEG + 255) / 256, 256, 0, s2>>>(segcnt);
    count_edges<<<(N_EDGES + 255) / 256, 256, 0, s2>>>(dst, etype, segcnt);
    scanA<<<scan_blocks, 1024, 0, s2>>>(segcnt, segoff, part);
    scanB<<<1, 256, 0, s2>>>(part, scan_blocks);
    scanC<<<scan_blocks, 1024, 0, s2>>>(segoff, cursor, part);
    scatter_edges<<<(N_EDGES + 255) / 256, 256, 0, s2>>>(src, dst, etype, cursor, esrc);
    init_out<<<(N_NODES * 2 + 255) / 256, 256, 0, s2>>>(out, b_out2);
    cudaEventRecord(eJoin, s2);

    // Main stream: weight prep + first two GEMMs (overlap the CSR branch)
    convert_weights<<<(1408 * 128 + 255) / 256, 256>>>(W_tweet, W_in, rgcn_root, rgcn_w, W_out1, blob);

    // t = lrelu(tweet @ W_tweet + b)  : fp32 in -> xA[:,0:128], B hi-plane only
    mma_gemm<32><<<gemm_blocks, 256>>>(nullptr, 0, 0, tweet, TWD,
                                       blob + BLOB_TWEET, TWD, 0, b_tweet,
                                       xA, XS, nullptr, nullptr, M, 1);
    // x = lrelu(t @ W_in + b)  : xA[:,0:128] -> xB[:,0:128], 2-term B
    mma_gemm<64><<<gemm_blocks, 256>>>(xA, XS, DD, nullptr, 0,
                                       blob + BLOB_WIN, DD, 1, b_in,
                                       xB, XS, nullptr, nullptr, M, 1);

    // Join: gathers need the CSR; final GEMM needs init_out
    cudaStreamWaitEvent(0, eJoin, 0);

    // conv1: means into xB[:,128:384]; combine xB[:,0:384] -> xA[:,0:128]
    gather_agg<<<(NSEG + 3) / 4, 256>>>(esrc, segoff, segcnt, (__half2*)xB);
    mma_gemm<64><<<gemm_blocks, 256>>>(xB, XS, 3 * DD, nullptr, 0,
                                       blob + BLOB_COMB, 3 * DD, 0, rgcn_b,
                                       xA, XS, nullptr, nullptr, M, 0);

    // conv2: means into xA[:,128:384]; combine xA[:,0:384] -> xB[:,0:128]
    gather_agg<<<(NSEG + 3) / 4, 256>>>(esrc, segoff, segcnt, (__half2*)xA);
    mma_gemm<64><<<gemm_blocks, 256>>>(xA, XS, 3 * DD, nullptr, 0,
                                       blob + BLOB_COMB, 3 * DD, 1, rgcn_b,
                                       xB, XS, nullptr, nullptr, M, 0);

    // fused: out = lrelu(xB[:,0:128] @ W_out1 + b_out1) @ W_out2 + b_out2
    mma_gemm<64><<<gemm_blocks, 256>>>(xB, XS, DD, nullptr, 0,
                                       blob + BLOB_WOUT1, DD, 1, b_out1,
                                       nullptr, 0, W_out2, out, M, 1);

    cudaEventDestroy(eFork);
    cudaEventDestroy(eJoin);
    cudaStreamDestroy(s2);
}